// round 8
// baseline (speedup 1.0000x reference)
#include <cuda_runtime.h>
#include <cuda_bf16.h>
#include <cstdint>
#include <cstddef>

// Problem dimensions (fixed by reference setup_inputs)
#define SS 2048
#define BB 2
#define HH 2048
#define NH 16
#define DD 128
#define SB (SS*BB)       // 4096 rows
#define H3 (3*HH)        // 6144

// ---------------------------------------------------------------------------
// Scratch (__device__ globals; allocation-free rule)
// ---------------------------------------------------------------------------
__device__ __nv_bfloat16 g_hidH[(size_t)SB*HH];
__device__ __nv_bfloat16 g_hidL[(size_t)SB*HH];
__device__ __nv_bfloat16 g_qwH[(size_t)H3*HH];   // qkv_w transposed [6144][2048]
__device__ __nv_bfloat16 g_qwL[(size_t)H3*HH];
__device__ __nv_bfloat16 g_ctxH[(size_t)SB*HH];  // attention writes these directly
__device__ __nv_bfloat16 g_ctxL[(size_t)SB*HH];
__device__ __nv_bfloat16 g_pwH[(size_t)HH*HH];   // proj_w transposed [2048][2048]
__device__ __nv_bfloat16 g_pwL[(size_t)HH*HH];

// attention operands, head-major [b,h,s,d] (V same layout; trans-ldmatrix in attn)
#define PLANE ((size_t)BB*NH*SS*DD)
__device__ __nv_bfloat16 g_qh[PLANE];
__device__ __nv_bfloat16 g_ql[PLANE];
__device__ __nv_bfloat16 g_kh[PLANE];
__device__ __nv_bfloat16 g_kl[PLANE];
__device__ __nv_bfloat16 g_vh[PLANE];
__device__ __nv_bfloat16 g_vl[PLANE];

// ---------------------------------------------------------------------------
// Base-PTX helpers (no 'a'-gated features: works on compute_103)
// ---------------------------------------------------------------------------
__device__ __forceinline__ uint32_t smem_to_u32(const void* p) {
    uint32_t a;
    asm("{ .reg .u64 t; cvta.to.shared.u64 t, %1; cvt.u32.u64 %0, t; }"
        : "=r"(a) : "l"(p));
    return a;
}

#define SMEM_SWZ64(b)  ((b) ^ (((b) >> 3) & 0x30))       // 64B rows
#define SMEM_SWZ256(b) ((b) ^ ((((b) >> 8) & 7u) << 4))  // 256B rows

#define CP_ASYNC16(dst, src) \
    asm volatile("cp.async.cg.shared.global [%0], [%1], 16;" \
                 :: "r"(dst), "l"(src) : "memory")
#define CP_COMMIT() asm volatile("cp.async.commit_group;" ::: "memory")
#define CP_WAIT2()  asm volatile("cp.async.wait_group 2;" ::: "memory")
#define CP_WAIT0()  asm volatile("cp.async.wait_group 0;" ::: "memory")

#define LDSM4(r0, r1, r2, r3, addr) \
    asm volatile("ldmatrix.sync.aligned.m8n8.x4.shared.b16 {%0,%1,%2,%3}, [%4];" \
                 : "=r"(r0), "=r"(r1), "=r"(r2), "=r"(r3) : "r"(addr))

#define LDSM4T(r0, r1, r2, r3, addr) \
    asm volatile("ldmatrix.sync.aligned.m8n8.x4.trans.shared.b16 {%0,%1,%2,%3}, [%4];" \
                 : "=r"(r0), "=r"(r1), "=r"(r2), "=r"(r3) : "r"(addr))

#define MMA16816(c, a, b0v, b1v) \
    asm volatile("mma.sync.aligned.m16n8k16.row.col.f32.bf16.bf16.f32 " \
                 "{%0,%1,%2,%3}, {%4,%5,%6,%7}, {%8,%9}, {%0,%1,%2,%3};" \
                 : "+f"((c)[0]), "+f"((c)[1]), "+f"((c)[2]), "+f"((c)[3]) \
                 : "r"((a)[0]), "r"((a)[1]), "r"((a)[2]), "r"((a)[3]), \
                   "r"(b0v), "r"(b1v))

// split-pack (x,y) into hi bf16x2 + lo bf16x2 words
__device__ __forceinline__ void splitpk(float x, float y, uint32_t& hi, uint32_t& lo) {
    __nv_bfloat16 hx = __float2bfloat16(x), hy = __float2bfloat16(y);
    float lx = x - __bfloat162float(hx), ly = y - __bfloat162float(hy);
    __nv_bfloat162 hp = __halves2bfloat162(hx, hy);
    __nv_bfloat162 lp = __floats2bfloat162_rn(lx, ly);
    hi = *reinterpret_cast<uint32_t*>(&hp);
    lo = *reinterpret_cast<uint32_t*>(&lp);
}

// ---------------------------------------------------------------------------
// Conversion kernels
// ---------------------------------------------------------------------------
__global__ void split_f32(const float* __restrict__ in,
                          __nv_bfloat16* __restrict__ hi,
                          __nv_bfloat16* __restrict__ lo, int n)
{
    int i4 = (blockIdx.x * blockDim.x + threadIdx.x) * 4;
    if (i4 >= n) return;
    float4 v = *(const float4*)(in + i4);
    uint32_t h0, l0, h1, l1;
    splitpk(v.x, v.y, h0, l0);
    splitpk(v.z, v.w, h1, l1);
    *(uint2*)(hi + i4) = make_uint2(h0, h1);
    *(uint2*)(lo + i4) = make_uint2(l0, l1);
}

// W[K][N] fp32 -> Wt[N][K] bf16 hi/lo (transpose + split)
__global__ void transpose_split(const float* __restrict__ W,
                                __nv_bfloat16* __restrict__ Th,
                                __nv_bfloat16* __restrict__ Tl, int K, int N)
{
    __shared__ float tile[32][33];
    int k0 = blockIdx.y * 32, n0 = blockIdx.x * 32;
    int tx = threadIdx.x, ty = threadIdx.y; // 32x8
#pragma unroll
    for (int r = 0; r < 32; r += 8)
        tile[ty + r][tx] = W[(size_t)(k0 + ty + r) * N + n0 + tx];
    __syncthreads();
#pragma unroll
    for (int r = 0; r < 32; r += 8) {
        float x = tile[tx][ty + r];
        __nv_bfloat16 h = __float2bfloat16(x);
        __nv_bfloat16 l = __float2bfloat16(x - __bfloat162float(h));
        size_t o = (size_t)(n0 + ty + r) * K + k0 + tx;
        Th[o] = h; Tl[o] = l;
    }
}

// ---------------------------------------------------------------------------
// mma.sync bf16-split GEMM — 4 warps (64x64 each), K-chunk 32, 3-stage pipe.
// EPI 0: fp32 C -> proj out.  EPI 1: split-write q/k/v planes (+bias).
// ---------------------------------------------------------------------------
#define GST 32768                    // per-stage bytes (4 x 8KB tiles)
#define GSM_BYTES (3*GST + 1024)

template<int EPI>
__global__ __launch_bounds__(128)
void gemm_mma_split(const __nv_bfloat16* __restrict__ Ah_,
                    const __nv_bfloat16* __restrict__ Al_,
                    const __nv_bfloat16* __restrict__ Bh_,
                    const __nv_bfloat16* __restrict__ Bl_,
                    const float* __restrict__ bias,
                    float* __restrict__ C, int M, int N, int K)
{
    extern __shared__ char dsm_raw[];
    uint32_t raw = smem_to_u32(dsm_raw);
    uint32_t base = (raw + 1023u) & ~1023u;

    const int tid  = threadIdx.x;
    const int lane = tid & 31;
    const int w    = tid >> 5;           // 0..3
    const int m0 = (w >> 1) * 64;        // warp row origin (0/64)
    const int n0 = (w & 1) * 64;         // warp col origin (0/64)
    const int bm = blockIdx.y * 128;
    const int bn = blockIdx.x * 128;

    const int agrp = lane >> 3;
    const int ar  = (lane & 7) + ((agrp & 1) << 3);
    const int acb = (agrp & 2) << 3;
    const int br  = (lane & 7) + ((agrp & 2) << 2);
    const int bcb = (agrp & 1) << 4;

    float acc[4][8][4];
#pragma unroll
    for (int i = 0; i < 4; i++)
#pragma unroll
        for (int j = 0; j < 8; j++)
#pragma unroll
            for (int v = 0; v < 4; v++) acc[i][j][v] = 0.f;

    auto load_chunk = [&](int stage, int k0) {
        uint32_t sb = base + stage * GST;
#pragma unroll
        for (int it = 0; it < 4; it++) {
            int idx = tid + it * 128;    // 0..511
            int row = idx >> 2;          // 0..127
            int seg = idx & 3;           // 16B segment within 64B row
            uint32_t sw = SMEM_SWZ64((uint32_t)(row * 64 + seg * 16));
            size_t ga = (size_t)(bm + row) * K + k0 + seg * 8;
            size_t gb = (size_t)(bn + row) * K + k0 + seg * 8;
            CP_ASYNC16(sb +     0 + sw, Ah_ + ga);
            CP_ASYNC16(sb +  8192 + sw, Al_ + ga);
            CP_ASYNC16(sb + 16384 + sw, Bh_ + gb);
            CP_ASYNC16(sb + 24576 + sw, Bl_ + gb);
        }
    };

    const int nch = K >> 5;              // K/32 chunks
    load_chunk(0, 0);  CP_COMMIT();
    load_chunk(1, 32); CP_COMMIT();

    for (int ch = 0; ch < nch; ch++) {
        if (ch + 2 < nch) load_chunk((ch + 2) % 3, (ch + 2) << 5);
        CP_COMMIT();                     // always commit (possibly empty group)
        CP_WAIT2();                      // chunk ch guaranteed complete
        __syncthreads();

        uint32_t sb = base + (ch % 3) * GST;
#pragma unroll
        for (int ks = 0; ks < 2; ks++) {
            uint32_t ah[4][4], al[4][4], bh[4][4], bl[4][4];
#pragma unroll
            for (int mt = 0; mt < 4; mt++) {
                uint32_t off = SMEM_SWZ64((uint32_t)((m0 + mt * 16 + ar) * 64 + ks * 32 + acb));
                LDSM4(ah[mt][0], ah[mt][1], ah[mt][2], ah[mt][3], sb + off);
                LDSM4(al[mt][0], al[mt][1], al[mt][2], al[mt][3], sb + 8192 + off);
            }
#pragma unroll
            for (int p = 0; p < 4; p++) {
                uint32_t off = SMEM_SWZ64((uint32_t)((n0 + p * 16 + br) * 64 + ks * 32 + bcb));
                LDSM4(bh[p][0], bh[p][1], bh[p][2], bh[p][3], sb + 16384 + off);
                LDSM4(bl[p][0], bl[p][1], bl[p][2], bl[p][3], sb + 24576 + off);
            }
#pragma unroll
            for (int mt = 0; mt < 4; mt++)
#pragma unroll
                for (int nt = 0; nt < 8; nt++) {
                    int p = nt >> 1, hh = (nt & 1) * 2;
                    MMA16816(acc[mt][nt], ah[mt], bh[p][hh], bh[p][hh + 1]);
                    MMA16816(acc[mt][nt], ah[mt], bl[p][hh], bl[p][hh + 1]);
                    MMA16816(acc[mt][nt], al[mt], bh[p][hh], bh[p][hh + 1]);
                }
        }
        __syncthreads();
    }

    const int gr = lane >> 2;
    const int gc = (lane & 3) * 2;

    if (EPI == 0) {
        // fp32 C, no bias (proj GEMM)
#pragma unroll
        for (int mt = 0; mt < 4; mt++) {
            int row0 = bm + m0 + mt * 16 + gr;
#pragma unroll
            for (int nt = 0; nt < 8; nt++) {
                int col = bn + n0 + nt * 8 + gc;
                float2 v0 = { acc[mt][nt][0], acc[mt][nt][1] };
                float2 v1 = { acc[mt][nt][2], acc[mt][nt][3] };
                *(float2*)&C[(size_t)row0 * N + col]       = v0;
                *(float2*)&C[(size_t)(row0 + 8) * N + col] = v1;
            }
        }
    } else {
        // QKV epilogue: add bias, split-pack, write head-major bf16 planes.
        const int h = bn / 384;
        const int part = (bn % 384) / 128;
        __nv_bfloat16* dh = (part == 0) ? g_qh : (part == 1) ? g_kh : g_vh;
        __nv_bfloat16* dl = (part == 0) ? g_ql : (part == 1) ? g_kl : g_vl;
#pragma unroll
        for (int mt = 0; mt < 4; mt++) {
            int row0 = bm + m0 + mt * 16 + gr;   // s*BB + b
            int b = row0 & 1;
            int s0 = row0 >> 1;
            int s1 = (row0 + 8) >> 1;
            size_t pl = ((size_t)(b * NH + h)) * SS;
#pragma unroll
            for (int nt = 0; nt < 8; nt++) {
                int d = n0 + nt * 8 + gc;
                float bx = bias[bn + d], by = bias[bn + d + 1];
                uint32_t hi, lo;
                size_t a0 = (pl + s0) * DD + d;
                splitpk(acc[mt][nt][0] + bx, acc[mt][nt][1] + by, hi, lo);
                *(uint32_t*)&dh[a0] = hi;
                *(uint32_t*)&dl[a0] = lo;
                size_t a1 = (pl + s1) * DD + d;
                splitpk(acc[mt][nt][2] + bx, acc[mt][nt][3] + by, hi, lo);
                *(uint32_t*)&dh[a1] = hi;
                *(uint32_t*)&dl[a1] = lo;
            }
        }
    }
}

// ---------------------------------------------------------------------------
// Tensor-core flash attention: bf16-split QK^T and PV, fp32 softmax.
// V kept in [s,d] layout; PV B-fragments via ldmatrix.trans.
// Block: (qt, b*NH+h). 128 threads = 4 warps, each warp 16 q-rows x 64 kv cols.
// qt reversed so longest (causal) blocks launch first.
// ---------------------------------------------------------------------------
#define ASM_BYTES (98304 + 1024)

__global__ __launch_bounds__(128)
void attn_mma()
{
    extern __shared__ char dsm_raw[];
    uint32_t raw = smem_to_u32(dsm_raw);
    uint32_t base = (raw + 1023u) & ~1023u;
    const uint32_t uQh = base,          uQl = base + 16384;
    const uint32_t uKh = base + 32768,  uKl = base + 49152;
    const uint32_t uVh = base + 65536,  uVl = base + 81920;

    const int qt = gridDim.x - 1 - blockIdx.x;   // longest blocks first
    const int bh = blockIdx.y;
    const int b = bh >> 4, h = bh & 15;
    const int tid = threadIdx.x, lane = tid & 31, warp = tid >> 5;

    const int agrp = lane >> 3;
    const int ar  = (lane & 7) + ((agrp & 1) << 3);
    const int acb = (agrp & 2) << 3;
    const int br  = (lane & 7) + ((agrp & 2) << 2);
    const int bcb = (agrp & 1) << 4;
    const int gr  = lane >> 2, gc = (lane & 3) * 2;
    const int vr  = (lane & 7) + ((agrp & 1) << 3);
    const int vcb = (agrp & 2) << 3;

    const size_t plane = ((size_t)(b * NH + h)) * SS * DD;
    const __nv_bfloat16* gqh = g_qh + plane;
    const __nv_bfloat16* gql = g_ql + plane;
    const __nv_bfloat16* gkh = g_kh + plane;
    const __nv_bfloat16* gkl = g_kl + plane;
    const __nv_bfloat16* gvh = g_vh + plane;   // [s][d]
    const __nv_bfloat16* gvl = g_vl + plane;

    // Q tile (64 x 128, hi+lo) — loaded once
#pragma unroll
    for (int i = 0; i < 8; i++) {
        int idx = tid + i * 128;
        int row = idx >> 4, seg = idx & 15;
        uint32_t sw = SMEM_SWZ256((uint32_t)(row * 256 + seg * 16));
        size_t g = (size_t)(qt * 64 + row) * DD + seg * 8;
        CP_ASYNC16(uQh + sw, gqh + g);
        CP_ASYNC16(uQl + sw, gql + g);
    }

    float m0 = -1e30f, m1 = -1e30f, l0 = 0.f, l1 = 0.f;
    float oa[16][4];
#pragma unroll
    for (int i = 0; i < 16; i++)
#pragma unroll
        for (int v = 0; v < 4; v++) oa[i][v] = 0.f;

    const float scale = 0.08838834764831845f; // 1/sqrt(128)
    const int row0 = qt * 64 + warp * 16 + gr;

    for (int kt = 0; kt <= qt; kt++) {
        __syncthreads();    // prior tile's compute done before K/V overwrite
#pragma unroll
        for (int i = 0; i < 8; i++) {
            int idx = tid + i * 128;
            int row = idx >> 4, seg = idx & 15;
            uint32_t sw = SMEM_SWZ256((uint32_t)(row * 256 + seg * 16));
            size_t g = (size_t)(kt * 64 + row) * DD + seg * 8;
            CP_ASYNC16(uKh + sw, gkh + g);
            CP_ASYNC16(uKl + sw, gkl + g);
            CP_ASYNC16(uVh + sw, gvh + g);
            CP_ASYNC16(uVl + sw, gvl + g);
        }
        CP_COMMIT(); CP_WAIT0(); __syncthreads();

        // ---- S = Q K^T (3-pass bf16 split) ----
        float sa[8][4];
#pragma unroll
        for (int i = 0; i < 8; i++)
#pragma unroll
            for (int v = 0; v < 4; v++) sa[i][v] = 0.f;

#pragma unroll
        for (int ks = 0; ks < 8; ks++) {
            uint32_t offa = SMEM_SWZ256((uint32_t)((warp * 16 + ar) * 256 + ks * 32 + acb));
            uint32_t ah[4], al[4];
            LDSM4(ah[0], ah[1], ah[2], ah[3], uQh + offa);
            LDSM4(al[0], al[1], al[2], al[3], uQl + offa);
            uint32_t bhf[4][4], blf[4][4];
#pragma unroll
            for (int p = 0; p < 4; p++) {
                uint32_t offb = SMEM_SWZ256((uint32_t)((p * 16 + br) * 256 + ks * 32 + bcb));
                LDSM4(bhf[p][0], bhf[p][1], bhf[p][2], bhf[p][3], uKh + offb);
                LDSM4(blf[p][0], blf[p][1], blf[p][2], blf[p][3], uKl + offb);
            }
#pragma unroll
            for (int nt = 0; nt < 8; nt++) {
                int p = nt >> 1, hh = (nt & 1) * 2;
                MMA16816(sa[nt], ah, bhf[p][hh], bhf[p][hh + 1]);
                MMA16816(sa[nt], ah, blf[p][hh], blf[p][hh + 1]);
                MMA16816(sa[nt], al, bhf[p][hh], bhf[p][hh + 1]);
            }
        }

        // ---- scale + causal mask ----
        if (kt == qt) {
#pragma unroll
            for (int nt = 0; nt < 8; nt++) {
                int col = kt * 64 + nt * 8 + gc;
                sa[nt][0] = (col     > row0    ) ? -10000.f : sa[nt][0] * scale;
                sa[nt][1] = (col + 1 > row0    ) ? -10000.f : sa[nt][1] * scale;
                sa[nt][2] = (col     > row0 + 8) ? -10000.f : sa[nt][2] * scale;
                sa[nt][3] = (col + 1 > row0 + 8) ? -10000.f : sa[nt][3] * scale;
            }
        } else {
#pragma unroll
            for (int nt = 0; nt < 8; nt++)
#pragma unroll
                for (int v = 0; v < 4; v++) sa[nt][v] *= scale;
        }

        // ---- online softmax (rows row0, row0+8) ----
        float tm0 = -1e30f, tm1 = -1e30f;
#pragma unroll
        for (int nt = 0; nt < 8; nt++) {
            tm0 = fmaxf(tm0, fmaxf(sa[nt][0], sa[nt][1]));
            tm1 = fmaxf(tm1, fmaxf(sa[nt][2], sa[nt][3]));
        }
        tm0 = fmaxf(tm0, __shfl_xor_sync(0xffffffffu, tm0, 1));
        tm0 = fmaxf(tm0, __shfl_xor_sync(0xffffffffu, tm0, 2));
        tm1 = fmaxf(tm1, __shfl_xor_sync(0xffffffffu, tm1, 1));
        tm1 = fmaxf(tm1, __shfl_xor_sync(0xffffffffu, tm1, 2));
        float m0n = fmaxf(m0, tm0), m1n = fmaxf(m1, tm1);
        float alpha0 = __expf(m0 - m0n), alpha1 = __expf(m1 - m1n);

        float sum0 = 0.f, sum1 = 0.f;
#pragma unroll
        for (int nt = 0; nt < 8; nt++) {
            sa[nt][0] = __expf(sa[nt][0] - m0n);
            sa[nt][1] = __expf(sa[nt][1] - m0n);
            sa[nt][2] = __expf(sa[nt][2] - m1n);
            sa[nt][3] = __expf(sa[nt][3] - m1n);
            sum0 += sa[nt][0] + sa[nt][1];
            sum1 += sa[nt][2] + sa[nt][3];
        }
        sum0 += __shfl_xor_sync(0xffffffffu, sum0, 1);
        sum0 += __shfl_xor_sync(0xffffffffu, sum0, 2);
        sum1 += __shfl_xor_sync(0xffffffffu, sum1, 1);
        sum1 += __shfl_xor_sync(0xffffffffu, sum1, 2);
        l0 = l0 * alpha0 + sum0; l1 = l1 * alpha1 + sum1;
        m0 = m0n; m1 = m1n;
#pragma unroll
        for (int i = 0; i < 16; i++) {
            oa[i][0] *= alpha0; oa[i][1] *= alpha0;
            oa[i][2] *= alpha1; oa[i][3] *= alpha1;
        }

        // ---- pack P into A-fragments (hi/lo) in registers ----
        uint32_t pah[4][4], pal[4][4];
#pragma unroll
        for (int k2 = 0; k2 < 4; k2++) {
            int t0 = 2 * k2, t1 = 2 * k2 + 1;
            splitpk(sa[t0][0], sa[t0][1], pah[k2][0], pal[k2][0]);
            splitpk(sa[t0][2], sa[t0][3], pah[k2][1], pal[k2][1]);
            splitpk(sa[t1][0], sa[t1][1], pah[k2][2], pal[k2][2]);
            splitpk(sa[t1][2], sa[t1][3], pah[k2][3], pal[k2][3]);
        }

        // ---- O += P V (3-pass bf16 split; V[s,d] via trans-ldmatrix) ----
#pragma unroll
        for (int k2 = 0; k2 < 4; k2++) {
#pragma unroll
            for (int p = 0; p < 8; p++) {
                uint32_t offv = SMEM_SWZ256((uint32_t)((k2 * 16 + vr) * 256 + p * 32 + vcb));
                uint32_t vh4[4], vl4[4];
                LDSM4T(vh4[0], vh4[1], vh4[2], vh4[3], uVh + offv);
                LDSM4T(vl4[0], vl4[1], vl4[2], vl4[3], uVl + offv);
                MMA16816(oa[2 * p    ], pah[k2], vh4[0], vh4[1]);
                MMA16816(oa[2 * p    ], pal[k2], vh4[0], vh4[1]);
                MMA16816(oa[2 * p    ], pah[k2], vl4[0], vl4[1]);
                MMA16816(oa[2 * p + 1], pah[k2], vh4[2], vh4[3]);
                MMA16816(oa[2 * p + 1], pal[k2], vh4[2], vh4[3]);
                MMA16816(oa[2 * p + 1], pah[k2], vl4[2], vl4[3]);
            }
        }
    }

    // ---- normalize + write ctx bf16 hi/lo [s,b,H] ----
    float inv0 = 1.f / l0, inv1 = 1.f / l1;
    int s0 = row0;
#pragma unroll
    for (int nt = 0; nt < 16; nt++) {
        int d0 = nt * 8 + gc;
        size_t a0 = ((size_t)(s0 * BB + b)) * HH + h * DD + d0;
        size_t a1 = ((size_t)((s0 + 8) * BB + b)) * HH + h * DD + d0;
        uint32_t hi, lo;
        splitpk(oa[nt][0] * inv0, oa[nt][1] * inv0, hi, lo);
        *(uint32_t*)&g_ctxH[a0] = hi;
        *(uint32_t*)&g_ctxL[a0] = lo;
        splitpk(oa[nt][2] * inv1, oa[nt][3] * inv1, hi, lo);
        *(uint32_t*)&g_ctxH[a1] = hi;
        *(uint32_t*)&g_ctxL[a1] = lo;
    }
}

__global__ void copy_bias_kernel(const float* __restrict__ bias,
                                 float* __restrict__ out, int n)
{
    int i = blockIdx.x * blockDim.x + threadIdx.x;
    if (i < n) out[i] = bias[i];
}

// ---------------------------------------------------------------------------
extern "C" void kernel_launch(void* const* d_in, const int* in_sizes, int n_in,
                              void* d_out, int out_size)
{
    const float* hidden  = (const float*)d_in[0];
    const float* qkv_w   = (const float*)d_in[2];
    const float* qkv_b   = (const float*)d_in[3];
    const float* proj_w  = (const float*)d_in[4];
    const float* proj_b  = (const float*)d_in[5];
    float* out = (float*)d_out;

    static bool init = false;
    static __nv_bfloat16 *hidH, *hidL, *qwH, *qwL, *ctxH, *ctxL, *pwH, *pwL;
    if (!init) {
        cudaGetSymbolAddress((void**)&hidH,  g_hidH);
        cudaGetSymbolAddress((void**)&hidL,  g_hidL);
        cudaGetSymbolAddress((void**)&qwH,   g_qwH);
        cudaGetSymbolAddress((void**)&qwL,   g_qwL);
        cudaGetSymbolAddress((void**)&ctxH,  g_ctxH);
        cudaGetSymbolAddress((void**)&ctxL,  g_ctxL);
        cudaGetSymbolAddress((void**)&pwH,   g_pwH);
        cudaGetSymbolAddress((void**)&pwL,   g_pwL);
        cudaFuncSetAttribute(gemm_mma_split<0>,
                             cudaFuncAttributeMaxDynamicSharedMemorySize, GSM_BYTES);
        cudaFuncSetAttribute(gemm_mma_split<1>,
                             cudaFuncAttributeMaxDynamicSharedMemorySize, GSM_BYTES);
        cudaFuncSetAttribute(attn_mma,
                             cudaFuncAttributeMaxDynamicSharedMemorySize, ASM_BYTES);
        init = true;
    }

    // 1) Split hidden + transpose/split qkv_w
    {
        int n = SB * HH;
        split_f32<<<n / 1024, 256>>>(hidden, hidH, hidL, n);
        dim3 tb(32, 8);
        transpose_split<<<dim3(H3 / 32, HH / 32), tb>>>(qkv_w, qwH, qwL, HH, H3);
    }

    // 2) QKV GEMM (tensor cores) -> bf16 hi/lo q/k/v planes directly
    gemm_mma_split<1><<<dim3(H3 / 128, SB / 128), 128, GSM_BYTES>>>(
        hidH, hidL, qwH, qwL, qkv_b, nullptr, SB, H3, HH);

    // 3) Tensor-core flash attention -> ctxH/ctxL bf16
    attn_mma<<<dim3(SS / 64, BB * NH), 128, ASM_BYTES>>>();

    // 4) transpose/split proj_w, then output projection
    {
        dim3 tb(32, 8);
        transpose_split<<<dim3(HH / 32, HH / 32), tb>>>(proj_w, pwH, pwL, HH, HH);
    }
    gemm_mma_split<0><<<dim3(HH / 128, SB / 128), 128, GSM_BYTES>>>(
        ctxH, ctxL, pwH, pwL, nullptr, out, SB, HH, HH);

    // 5) Second tuple element: proj_bias
    int extra = out_size - SB * HH;
    if (extra > 0) {
        copy_bias_kernel<<<(extra + 255) / 256, 256>>>(proj_b, out + (size_t)SB * HH, extra);
    }
}

// round 9
// speedup vs baseline: 1.5581x; 1.5581x over previous
#include <cuda_runtime.h>
#include <cuda_bf16.h>
#include <cstdint>
#include <cstddef>

// Problem dimensions (fixed by reference setup_inputs)
#define SS 2048
#define BB 2
#define HH 2048
#define NH 16
#define DD 128
#define SB (SS*BB)       // 4096 rows
#define H3 (3*HH)        // 6144

// ---------------------------------------------------------------------------
// Scratch (__device__ globals; allocation-free rule)
// ---------------------------------------------------------------------------
__device__ __nv_bfloat16 g_hidH[(size_t)SB*HH];
__device__ __nv_bfloat16 g_hidL[(size_t)SB*HH];
__device__ __nv_bfloat16 g_qwH[(size_t)H3*HH];   // qkv_w transposed [6144][2048]
__device__ __nv_bfloat16 g_qwL[(size_t)H3*HH];
__device__ __nv_bfloat16 g_ctxH[(size_t)SB*HH];  // attention writes these directly
__device__ __nv_bfloat16 g_ctxL[(size_t)SB*HH];
__device__ __nv_bfloat16 g_pwH[(size_t)HH*HH];   // proj_w transposed [2048][2048]
__device__ __nv_bfloat16 g_pwL[(size_t)HH*HH];

// attention operands, head-major [b,h,s,d] (V same layout; trans-ldmatrix in attn)
#define PLANE ((size_t)BB*NH*SS*DD)
__device__ __nv_bfloat16 g_qh[PLANE];
__device__ __nv_bfloat16 g_ql[PLANE];
__device__ __nv_bfloat16 g_kh[PLANE];
__device__ __nv_bfloat16 g_kl[PLANE];
__device__ __nv_bfloat16 g_vh[PLANE];
__device__ __nv_bfloat16 g_vl[PLANE];

// ---------------------------------------------------------------------------
// Base-PTX helpers (no 'a'-gated features: works on compute_103)
// ---------------------------------------------------------------------------
__device__ __forceinline__ uint32_t smem_to_u32(const void* p) {
    uint32_t a;
    asm("{ .reg .u64 t; cvta.to.shared.u64 t, %1; cvt.u32.u64 %0, t; }"
        : "=r"(a) : "l"(p));
    return a;
}

#define SMEM_SWZ64(b)  ((b) ^ (((b) >> 3) & 0x30))       // 64B rows
#define SMEM_SWZ256(b) ((b) ^ ((((b) >> 8) & 7u) << 4))  // 256B rows

#define CP_ASYNC16(dst, src) \
    asm volatile("cp.async.cg.shared.global [%0], [%1], 16;" \
                 :: "r"(dst), "l"(src) : "memory")
#define CP_COMMIT() asm volatile("cp.async.commit_group;" ::: "memory")
#define CP_WAIT1()  asm volatile("cp.async.wait_group 1;" ::: "memory")
#define CP_WAIT0()  asm volatile("cp.async.wait_group 0;" ::: "memory")

#define LDSM4(r0, r1, r2, r3, addr) \
    asm volatile("ldmatrix.sync.aligned.m8n8.x4.shared.b16 {%0,%1,%2,%3}, [%4];" \
                 : "=r"(r0), "=r"(r1), "=r"(r2), "=r"(r3) : "r"(addr))

#define LDSM4T(r0, r1, r2, r3, addr) \
    asm volatile("ldmatrix.sync.aligned.m8n8.x4.trans.shared.b16 {%0,%1,%2,%3}, [%4];" \
                 : "=r"(r0), "=r"(r1), "=r"(r2), "=r"(r3) : "r"(addr))

#define MMA16816(c, a, b0v, b1v) \
    asm volatile("mma.sync.aligned.m16n8k16.row.col.f32.bf16.bf16.f32 " \
                 "{%0,%1,%2,%3}, {%4,%5,%6,%7}, {%8,%9}, {%0,%1,%2,%3};" \
                 : "+f"((c)[0]), "+f"((c)[1]), "+f"((c)[2]), "+f"((c)[3]) \
                 : "r"((a)[0]), "r"((a)[1]), "r"((a)[2]), "r"((a)[3]), \
                   "r"(b0v), "r"(b1v))

// split-pack (x,y) into hi bf16x2 + lo bf16x2 words
__device__ __forceinline__ void splitpk(float x, float y, uint32_t& hi, uint32_t& lo) {
    __nv_bfloat16 hx = __float2bfloat16(x), hy = __float2bfloat16(y);
    float lx = x - __bfloat162float(hx), ly = y - __bfloat162float(hy);
    __nv_bfloat162 hp = __halves2bfloat162(hx, hy);
    __nv_bfloat162 lp = __floats2bfloat162_rn(lx, ly);
    hi = *reinterpret_cast<uint32_t*>(&hp);
    lo = *reinterpret_cast<uint32_t*>(&lp);
}

// ---------------------------------------------------------------------------
// Conversion kernels
// ---------------------------------------------------------------------------
__global__ void split_f32(const float* __restrict__ in,
                          __nv_bfloat16* __restrict__ hi,
                          __nv_bfloat16* __restrict__ lo, int n)
{
    int i4 = (blockIdx.x * blockDim.x + threadIdx.x) * 4;
    if (i4 >= n) return;
    float4 v = *(const float4*)(in + i4);
    uint32_t h0, l0, h1, l1;
    splitpk(v.x, v.y, h0, l0);
    splitpk(v.z, v.w, h1, l1);
    *(uint2*)(hi + i4) = make_uint2(h0, h1);
    *(uint2*)(lo + i4) = make_uint2(l0, l1);
}

// W[K][N] fp32 -> Wt[N][K] bf16 hi/lo (transpose + split)
__global__ void transpose_split(const float* __restrict__ W,
                                __nv_bfloat16* __restrict__ Th,
                                __nv_bfloat16* __restrict__ Tl, int K, int N)
{
    __shared__ float tile[32][33];
    int k0 = blockIdx.y * 32, n0 = blockIdx.x * 32;
    int tx = threadIdx.x, ty = threadIdx.y; // 32x8
#pragma unroll
    for (int r = 0; r < 32; r += 8)
        tile[ty + r][tx] = W[(size_t)(k0 + ty + r) * N + n0 + tx];
    __syncthreads();
#pragma unroll
    for (int r = 0; r < 32; r += 8) {
        float x = tile[tx][ty + r];
        __nv_bfloat16 h = __float2bfloat16(x);
        __nv_bfloat16 l = __float2bfloat16(x - __bfloat162float(h));
        size_t o = (size_t)(n0 + ty + r) * K + k0 + tx;
        Th[o] = h; Tl[o] = l;
    }
}

// ---------------------------------------------------------------------------
// mma.sync bf16-split GEMM — 8 warps (64x32 each), K-chunk 32, 2-stage pipe.
// 32KB/stage -> 66KB total -> 2 blocks/SM.  Regs held < 128 (launch_bounds).
// EPI 0: fp32 C -> proj out.  EPI 1: split-write q/k/v planes (+bias).
// ---------------------------------------------------------------------------
#define GST 32768                    // per-stage bytes (4 x 8KB tiles)
#define GSM_BYTES (2*GST + 1024)

template<int EPI>
__global__ __launch_bounds__(256, 2)
void gemm_mma_split(const __nv_bfloat16* __restrict__ Ah_,
                    const __nv_bfloat16* __restrict__ Al_,
                    const __nv_bfloat16* __restrict__ Bh_,
                    const __nv_bfloat16* __restrict__ Bl_,
                    const float* __restrict__ bias,
                    float* __restrict__ C, int M, int N, int K)
{
    extern __shared__ char dsm_raw[];
    uint32_t raw = smem_to_u32(dsm_raw);
    uint32_t base = (raw + 1023u) & ~1023u;

    const int tid  = threadIdx.x;
    const int lane = tid & 31;
    const int wid  = tid >> 5;
    const int m0 = (wid >> 2) * 64;      // warp row origin (0/64)
    const int n0 = (wid & 3) * 32;       // warp col origin (0..96)
    const int bm = blockIdx.y * 128;
    const int bn = blockIdx.x * 128;

    const int agrp = lane >> 3;
    const int ar  = (lane & 7) + ((agrp & 1) << 3);
    const int acb = (agrp & 2) << 3;
    const int br  = (lane & 7) + ((agrp & 2) << 2);
    const int bcb = (agrp & 1) << 4;

    float acc[4][4][4];
#pragma unroll
    for (int i = 0; i < 4; i++)
#pragma unroll
        for (int j = 0; j < 4; j++)
#pragma unroll
            for (int v = 0; v < 4; v++) acc[i][j][v] = 0.f;

    auto load_chunk = [&](int stage, int k0) {
        uint32_t sb = base + stage * GST;
#pragma unroll
        for (int it = 0; it < 2; it++) {
            int idx = tid + it * 256;    // 0..511
            int row = idx >> 2;          // 0..127
            int seg = idx & 3;           // 16B segment within 64B row
            uint32_t sw = SMEM_SWZ64((uint32_t)(row * 64 + seg * 16));
            size_t ga = (size_t)(bm + row) * K + k0 + seg * 8;
            size_t gb = (size_t)(bn + row) * K + k0 + seg * 8;
            CP_ASYNC16(sb +     0 + sw, Ah_ + ga);
            CP_ASYNC16(sb +  8192 + sw, Al_ + ga);
            CP_ASYNC16(sb + 16384 + sw, Bh_ + gb);
            CP_ASYNC16(sb + 24576 + sw, Bl_ + gb);
        }
        CP_COMMIT();
    };

    const int nch = K >> 5;              // K/32 chunks
    load_chunk(0, 0);

    for (int ch = 0; ch < nch; ch++) {
        if (ch + 1 < nch) { load_chunk((ch + 1) & 1, (ch + 1) << 5); CP_WAIT1(); }
        else              { CP_WAIT0(); }
        __syncthreads();

        uint32_t sb = base + (ch & 1) * GST;
#pragma unroll
        for (int ks = 0; ks < 2; ks++) {
            uint32_t bh[2][4], bl[2][4];
#pragma unroll
            for (int p = 0; p < 2; p++) {
                uint32_t off = SMEM_SWZ64((uint32_t)((n0 + p * 16 + br) * 64 + ks * 32 + bcb));
                LDSM4(bh[p][0], bh[p][1], bh[p][2], bh[p][3], sb + 16384 + off);
                LDSM4(bl[p][0], bl[p][1], bl[p][2], bl[p][3], sb + 24576 + off);
            }
#pragma unroll
            for (int mt = 0; mt < 4; mt++) {
                uint32_t off = SMEM_SWZ64((uint32_t)((m0 + mt * 16 + ar) * 64 + ks * 32 + acb));
                uint32_t ah[4], al[4];
                LDSM4(ah[0], ah[1], ah[2], ah[3], sb + off);
                LDSM4(al[0], al[1], al[2], al[3], sb + 8192 + off);
#pragma unroll
                for (int nt = 0; nt < 4; nt++) {
                    int p = nt >> 1, hh = (nt & 1) * 2;
                    MMA16816(acc[mt][nt], ah, bh[p][hh], bh[p][hh + 1]);
                    MMA16816(acc[mt][nt], ah, bl[p][hh], bl[p][hh + 1]);
                    MMA16816(acc[mt][nt], al, bh[p][hh], bh[p][hh + 1]);
                }
            }
        }
        __syncthreads();
    }

    const int gr = lane >> 2;
    const int gc = (lane & 3) * 2;

    if (EPI == 0) {
        // fp32 C, no bias (proj GEMM)
#pragma unroll
        for (int mt = 0; mt < 4; mt++) {
            int row0 = bm + m0 + mt * 16 + gr;
#pragma unroll
            for (int nt = 0; nt < 4; nt++) {
                int col = bn + n0 + nt * 8 + gc;
                float2 v0 = { acc[mt][nt][0], acc[mt][nt][1] };
                float2 v1 = { acc[mt][nt][2], acc[mt][nt][3] };
                *(float2*)&C[(size_t)row0 * N + col]       = v0;
                *(float2*)&C[(size_t)(row0 + 8) * N + col] = v1;
            }
        }
    } else {
        // QKV epilogue: add bias, split-pack, write head-major bf16 planes.
        const int h = bn / 384;
        const int part = (bn % 384) / 128;
        __nv_bfloat16* dh = (part == 0) ? g_qh : (part == 1) ? g_kh : g_vh;
        __nv_bfloat16* dl = (part == 0) ? g_ql : (part == 1) ? g_kl : g_vl;
#pragma unroll
        for (int mt = 0; mt < 4; mt++) {
            int row0 = bm + m0 + mt * 16 + gr;   // s*BB + b
            int b = row0 & 1;
            int s0 = row0 >> 1;
            int s1 = (row0 + 8) >> 1;
            size_t pl = ((size_t)(b * NH + h)) * SS;
#pragma unroll
            for (int nt = 0; nt < 4; nt++) {
                int d = n0 + nt * 8 + gc;
                float bx = bias[bn + d], by = bias[bn + d + 1];
                uint32_t hi, lo;
                size_t a0 = (pl + s0) * DD + d;
                splitpk(acc[mt][nt][0] + bx, acc[mt][nt][1] + by, hi, lo);
                *(uint32_t*)&dh[a0] = hi;
                *(uint32_t*)&dl[a0] = lo;
                size_t a1 = (pl + s1) * DD + d;
                splitpk(acc[mt][nt][2] + bx, acc[mt][nt][3] + by, hi, lo);
                *(uint32_t*)&dh[a1] = hi;
                *(uint32_t*)&dl[a1] = lo;
            }
        }
    }
}

// ---------------------------------------------------------------------------
// Tensor-core flash attention: bf16-split QK^T and PV, fp32 softmax.
// (exact R7-passing version: forward qt order)
// ---------------------------------------------------------------------------
#define ASM_BYTES (98304 + 1024)

__global__ __launch_bounds__(128)
void attn_mma()
{
    extern __shared__ char dsm_raw[];
    uint32_t raw = smem_to_u32(dsm_raw);
    uint32_t base = (raw + 1023u) & ~1023u;
    const uint32_t uQh = base,          uQl = base + 16384;
    const uint32_t uKh = base + 32768,  uKl = base + 49152;
    const uint32_t uVh = base + 65536,  uVl = base + 81920;

    const int qt = blockIdx.x, bh = blockIdx.y;
    const int b = bh >> 4, h = bh & 15;
    const int tid = threadIdx.x, lane = tid & 31, warp = tid >> 5;

    const int agrp = lane >> 3;
    const int ar  = (lane & 7) + ((agrp & 1) << 3);
    const int acb = (agrp & 2) << 3;
    const int br  = (lane & 7) + ((agrp & 2) << 2);
    const int bcb = (agrp & 1) << 4;
    const int gr  = lane >> 2, gc = (lane & 3) * 2;
    const int vr  = (lane & 7) + ((agrp & 1) << 3);
    const int vcb = (agrp & 2) << 3;

    const size_t plane = ((size_t)(b * NH + h)) * SS * DD;
    const __nv_bfloat16* gqh = g_qh + plane;
    const __nv_bfloat16* gql = g_ql + plane;
    const __nv_bfloat16* gkh = g_kh + plane;
    const __nv_bfloat16* gkl = g_kl + plane;
    const __nv_bfloat16* gvh = g_vh + plane;   // [s][d]
    const __nv_bfloat16* gvl = g_vl + plane;

    // Q tile (64 x 128, hi+lo) — loaded once
#pragma unroll
    for (int i = 0; i < 8; i++) {
        int idx = tid + i * 128;
        int row = idx >> 4, seg = idx & 15;
        uint32_t sw = SMEM_SWZ256((uint32_t)(row * 256 + seg * 16));
        size_t g = (size_t)(qt * 64 + row) * DD + seg * 8;
        CP_ASYNC16(uQh + sw, gqh + g);
        CP_ASYNC16(uQl + sw, gql + g);
    }

    float m0 = -1e30f, m1 = -1e30f, l0 = 0.f, l1 = 0.f;
    float oa[16][4];
#pragma unroll
    for (int i = 0; i < 16; i++)
#pragma unroll
        for (int v = 0; v < 4; v++) oa[i][v] = 0.f;

    const float scale = 0.08838834764831845f; // 1/sqrt(128)
    const int row0 = qt * 64 + warp * 16 + gr;

    for (int kt = 0; kt <= qt; kt++) {
        __syncthreads();    // prior tile's compute done before K/V overwrite
#pragma unroll
        for (int i = 0; i < 8; i++) {
            int idx = tid + i * 128;
            int row = idx >> 4, seg = idx & 15;
            uint32_t sw = SMEM_SWZ256((uint32_t)(row * 256 + seg * 16));
            size_t g = (size_t)(kt * 64 + row) * DD + seg * 8;
            CP_ASYNC16(uKh + sw, gkh + g);
            CP_ASYNC16(uKl + sw, gkl + g);
            CP_ASYNC16(uVh + sw, gvh + g);
            CP_ASYNC16(uVl + sw, gvl + g);
        }
        CP_COMMIT(); CP_WAIT0(); __syncthreads();

        // ---- S = Q K^T (3-pass bf16 split) ----
        float sa[8][4];
#pragma unroll
        for (int i = 0; i < 8; i++)
#pragma unroll
            for (int v = 0; v < 4; v++) sa[i][v] = 0.f;

#pragma unroll
        for (int ks = 0; ks < 8; ks++) {
            uint32_t offa = SMEM_SWZ256((uint32_t)((warp * 16 + ar) * 256 + ks * 32 + acb));
            uint32_t ah[4], al[4];
            LDSM4(ah[0], ah[1], ah[2], ah[3], uQh + offa);
            LDSM4(al[0], al[1], al[2], al[3], uQl + offa);
            uint32_t bhf[4][4], blf[4][4];
#pragma unroll
            for (int p = 0; p < 4; p++) {
                uint32_t offb = SMEM_SWZ256((uint32_t)((p * 16 + br) * 256 + ks * 32 + bcb));
                LDSM4(bhf[p][0], bhf[p][1], bhf[p][2], bhf[p][3], uKh + offb);
                LDSM4(blf[p][0], blf[p][1], blf[p][2], blf[p][3], uKl + offb);
            }
#pragma unroll
            for (int nt = 0; nt < 8; nt++) {
                int p = nt >> 1, hh = (nt & 1) * 2;
                MMA16816(sa[nt], ah, bhf[p][hh], bhf[p][hh + 1]);
                MMA16816(sa[nt], ah, blf[p][hh], blf[p][hh + 1]);
                MMA16816(sa[nt], al, bhf[p][hh], bhf[p][hh + 1]);
            }
        }

        // ---- scale + causal mask ----
        if (kt == qt) {
#pragma unroll
            for (int nt = 0; nt < 8; nt++) {
                int col = kt * 64 + nt * 8 + gc;
                sa[nt][0] = (col     > row0    ) ? -10000.f : sa[nt][0] * scale;
                sa[nt][1] = (col + 1 > row0    ) ? -10000.f : sa[nt][1] * scale;
                sa[nt][2] = (col     > row0 + 8) ? -10000.f : sa[nt][2] * scale;
                sa[nt][3] = (col + 1 > row0 + 8) ? -10000.f : sa[nt][3] * scale;
            }
        } else {
#pragma unroll
            for (int nt = 0; nt < 8; nt++)
#pragma unroll
                for (int v = 0; v < 4; v++) sa[nt][v] *= scale;
        }

        // ---- online softmax (rows row0, row0+8) ----
        float tm0 = -1e30f, tm1 = -1e30f;
#pragma unroll
        for (int nt = 0; nt < 8; nt++) {
            tm0 = fmaxf(tm0, fmaxf(sa[nt][0], sa[nt][1]));
            tm1 = fmaxf(tm1, fmaxf(sa[nt][2], sa[nt][3]));
        }
        tm0 = fmaxf(tm0, __shfl_xor_sync(0xffffffffu, tm0, 1));
        tm0 = fmaxf(tm0, __shfl_xor_sync(0xffffffffu, tm0, 2));
        tm1 = fmaxf(tm1, __shfl_xor_sync(0xffffffffu, tm1, 1));
        tm1 = fmaxf(tm1, __shfl_xor_sync(0xffffffffu, tm1, 2));
        float m0n = fmaxf(m0, tm0), m1n = fmaxf(m1, tm1);
        float alpha0 = __expf(m0 - m0n), alpha1 = __expf(m1 - m1n);

        float sum0 = 0.f, sum1 = 0.f;
#pragma unroll
        for (int nt = 0; nt < 8; nt++) {
            sa[nt][0] = __expf(sa[nt][0] - m0n);
            sa[nt][1] = __expf(sa[nt][1] - m0n);
            sa[nt][2] = __expf(sa[nt][2] - m1n);
            sa[nt][3] = __expf(sa[nt][3] - m1n);
            sum0 += sa[nt][0] + sa[nt][1];
            sum1 += sa[nt][2] + sa[nt][3];
        }
        sum0 += __shfl_xor_sync(0xffffffffu, sum0, 1);
        sum0 += __shfl_xor_sync(0xffffffffu, sum0, 2);
        sum1 += __shfl_xor_sync(0xffffffffu, sum1, 1);
        sum1 += __shfl_xor_sync(0xffffffffu, sum1, 2);
        l0 = l0 * alpha0 + sum0; l1 = l1 * alpha1 + sum1;
        m0 = m0n; m1 = m1n;
#pragma unroll
        for (int i = 0; i < 16; i++) {
            oa[i][0] *= alpha0; oa[i][1] *= alpha0;
            oa[i][2] *= alpha1; oa[i][3] *= alpha1;
        }

        // ---- pack P into A-fragments (hi/lo) in registers ----
        uint32_t pah[4][4], pal[4][4];
#pragma unroll
        for (int k2 = 0; k2 < 4; k2++) {
            int t0 = 2 * k2, t1 = 2 * k2 + 1;
            splitpk(sa[t0][0], sa[t0][1], pah[k2][0], pal[k2][0]);
            splitpk(sa[t0][2], sa[t0][3], pah[k2][1], pal[k2][1]);
            splitpk(sa[t1][0], sa[t1][1], pah[k2][2], pal[k2][2]);
            splitpk(sa[t1][2], sa[t1][3], pah[k2][3], pal[k2][3]);
        }

        // ---- O += P V (3-pass bf16 split; V[s,d] via trans-ldmatrix) ----
#pragma unroll
        for (int k2 = 0; k2 < 4; k2++) {
#pragma unroll
            for (int p = 0; p < 8; p++) {
                uint32_t offv = SMEM_SWZ256((uint32_t)((k2 * 16 + vr) * 256 + p * 32 + vcb));
                uint32_t vh4[4], vl4[4];
                LDSM4T(vh4[0], vh4[1], vh4[2], vh4[3], uVh + offv);
                LDSM4T(vl4[0], vl4[1], vl4[2], vl4[3], uVl + offv);
                MMA16816(oa[2 * p    ], pah[k2], vh4[0], vh4[1]);
                MMA16816(oa[2 * p    ], pal[k2], vh4[0], vh4[1]);
                MMA16816(oa[2 * p    ], pah[k2], vl4[0], vl4[1]);
                MMA16816(oa[2 * p + 1], pah[k2], vh4[2], vh4[3]);
                MMA16816(oa[2 * p + 1], pal[k2], vh4[2], vh4[3]);
                MMA16816(oa[2 * p + 1], pah[k2], vl4[2], vl4[3]);
            }
        }
    }

    // ---- normalize + write ctx bf16 hi/lo [s,b,H] ----
    float inv0 = 1.f / l0, inv1 = 1.f / l1;
    int s0 = row0;
#pragma unroll
    for (int nt = 0; nt < 16; nt++) {
        int d0 = nt * 8 + gc;
        size_t a0 = ((size_t)(s0 * BB + b)) * HH + h * DD + d0;
        size_t a1 = ((size_t)((s0 + 8) * BB + b)) * HH + h * DD + d0;
        uint32_t hi, lo;
        splitpk(oa[nt][0] * inv0, oa[nt][1] * inv0, hi, lo);
        *(uint32_t*)&g_ctxH[a0] = hi;
        *(uint32_t*)&g_ctxL[a0] = lo;
        splitpk(oa[nt][2] * inv1, oa[nt][3] * inv1, hi, lo);
        *(uint32_t*)&g_ctxH[a1] = hi;
        *(uint32_t*)&g_ctxL[a1] = lo;
    }
}

__global__ void copy_bias_kernel(const float* __restrict__ bias,
                                 float* __restrict__ out, int n)
{
    int i = blockIdx.x * blockDim.x + threadIdx.x;
    if (i < n) out[i] = bias[i];
}

// ---------------------------------------------------------------------------
extern "C" void kernel_launch(void* const* d_in, const int* in_sizes, int n_in,
                              void* d_out, int out_size)
{
    const float* hidden  = (const float*)d_in[0];
    const float* qkv_w   = (const float*)d_in[2];
    const float* qkv_b   = (const float*)d_in[3];
    const float* proj_w  = (const float*)d_in[4];
    const float* proj_b  = (const float*)d_in[5];
    float* out = (float*)d_out;

    static bool init = false;
    static __nv_bfloat16 *hidH, *hidL, *qwH, *qwL, *ctxH, *ctxL, *pwH, *pwL;
    if (!init) {
        cudaGetSymbolAddress((void**)&hidH,  g_hidH);
        cudaGetSymbolAddress((void**)&hidL,  g_hidL);
        cudaGetSymbolAddress((void**)&qwH,   g_qwH);
        cudaGetSymbolAddress((void**)&qwL,   g_qwL);
        cudaGetSymbolAddress((void**)&ctxH,  g_ctxH);
        cudaGetSymbolAddress((void**)&ctxL,  g_ctxL);
        cudaGetSymbolAddress((void**)&pwH,   g_pwH);
        cudaGetSymbolAddress((void**)&pwL,   g_pwL);
        cudaFuncSetAttribute(gemm_mma_split<0>,
                             cudaFuncAttributeMaxDynamicSharedMemorySize, GSM_BYTES);
        cudaFuncSetAttribute(gemm_mma_split<1>,
                             cudaFuncAttributeMaxDynamicSharedMemorySize, GSM_BYTES);
        cudaFuncSetAttribute(attn_mma,
                             cudaFuncAttributeMaxDynamicSharedMemorySize, ASM_BYTES);
        init = true;
    }

    // 1) Split hidden + transpose/split qkv_w
    {
        int n = SB * HH;
        split_f32<<<n / 1024, 256>>>(hidden, hidH, hidL, n);
        dim3 tb(32, 8);
        transpose_split<<<dim3(H3 / 32, HH / 32), tb>>>(qkv_w, qwH, qwL, HH, H3);
    }

    // 2) QKV GEMM (tensor cores) -> bf16 hi/lo q/k/v planes directly
    gemm_mma_split<1><<<dim3(H3 / 128, SB / 128), 256, GSM_BYTES>>>(
        hidH, hidL, qwH, qwL, qkv_b, nullptr, SB, H3, HH);

    // 3) Tensor-core flash attention -> ctxH/ctxL bf16
    attn_mma<<<dim3(SS / 64, BB * NH), 128, ASM_BYTES>>>();

    // 4) transpose/split proj_w, then output projection
    {
        dim3 tb(32, 8);
        transpose_split<<<dim3(HH / 32, HH / 32), tb>>>(proj_w, pwH, pwL, HH, HH);
    }
    gemm_mma_split<0><<<dim3(HH / 128, SB / 128), 256, GSM_BYTES>>>(
        ctxH, ctxL, pwH, pwL, nullptr, out, SB, HH, HH);

    // 5) Second tuple element: proj_bias
    int extra = out_size - SB * HH;
    if (extra > 0) {
        copy_bias_kernel<<<(extra + 255) / 256, 256>>>(proj_b, out + (size_t)SB * HH, extra);
    }
}